// round 1
// baseline (speedup 1.0000x reference)
#include <cuda_runtime.h>

#define SEQ   2048
#define HDIM  64
#define NHEAD 8
#define CDIM  512
#define NBH   16            // B*H
#define QKSCALE 0.125f

// ---------------- scratch (device globals; no allocation) ----------------
__device__ float g_Qh[NBH * SEQ * HDIM];
__device__ float g_Kh[NBH * SEQ * HDIM];
__device__ float g_Vh[NBH * SEQ * HDIM];
__device__ float g_S[(size_t)NBH * SEQ * SEQ];   // 268 MB
__device__ float g_X[2 * SEQ * CDIM];
__device__ int   g_q2k[NBH * SEQ];
__device__ int   g_k2q[NBH * SEQ];
__device__ float g_madd[NBH * SEQ];
__device__ float g_rmax[NBH * SEQ];
__device__ float g_rinv[NBH * SEQ];

// fast exp on the FMA pipe (avoids MUFU throughput wall). |rel err| ~1e-7.
__device__ __forceinline__ float fexp(float x) {
    float y = x * 1.4426950408889634f;
    y = fminf(fmaxf(y, -126.0f), 126.0f);
    float t = y + 12582912.0f;                 // round-to-nearest magic
    int   e = __float_as_int(t) - 0x4B400000;  // integer part
    float r = t - 12582912.0f;
    float f = y - r;                           // f in [-0.5, 0.5]
    float p = 1.535336188319500e-4f;
    p = fmaf(p, f, 1.339887440266574e-3f);
    p = fmaf(p, f, 9.618437357674640e-3f);
    p = fmaf(p, f, 5.550332471162809e-2f);
    p = fmaf(p, f, 2.402264791363012e-1f);
    p = fmaf(p, f, 6.931472028550421e-1f);
    p = fmaf(p, f, 1.0f);
    return p * __int_as_float((e + 127) << 23);
}

#define FMA16(a, b, acc)                                                   \
    acc[0][0] = fmaf(a.x, b.x, acc[0][0]); acc[0][1] = fmaf(a.x, b.y, acc[0][1]); \
    acc[0][2] = fmaf(a.x, b.z, acc[0][2]); acc[0][3] = fmaf(a.x, b.w, acc[0][3]); \
    acc[1][0] = fmaf(a.y, b.x, acc[1][0]); acc[1][1] = fmaf(a.y, b.y, acc[1][1]); \
    acc[1][2] = fmaf(a.y, b.z, acc[1][2]); acc[1][3] = fmaf(a.y, b.w, acc[1][3]); \
    acc[2][0] = fmaf(a.z, b.x, acc[2][0]); acc[2][1] = fmaf(a.z, b.y, acc[2][1]); \
    acc[2][2] = fmaf(a.z, b.z, acc[2][2]); acc[2][3] = fmaf(a.z, b.w, acc[2][3]); \
    acc[3][0] = fmaf(a.w, b.x, acc[3][0]); acc[3][1] = fmaf(a.w, b.y, acc[3][1]); \
    acc[3][2] = fmaf(a.w, b.z, acc[3][2]); acc[3][3] = fmaf(a.w, b.w, acc[3][3]);

// ---------------- projection GEMM: C = A @ W^T, M=4096, N=K=512 ----------
// mode 0/1/2: scatter into g_Qh/g_Kh/g_Vh head layout [B,H,seq,HD]
// mode 3: plain row-major write to outPlain [4096,512]
__global__ void proj_kernel(const float* __restrict__ A,
                            const float* __restrict__ W,
                            float* __restrict__ outPlain, int mode)
{
    __shared__ float As[16][68];
    __shared__ float Bs[16][68];
    const int tid = threadIdx.x;
    const int r0 = blockIdx.y << 6, c0 = blockIdx.x << 6;
    const int lr = tid >> 2;
    const int lc = (tid & 3) << 2;
    const float* Ap = A + (size_t)(r0 + lr) * CDIM + lc;
    const float* Wp = W + (size_t)(c0 + lr) * CDIM + lc;
    const int ty = tid >> 4, tx = tid & 15;
    float acc[4][4] = {};

    for (int k0 = 0; k0 < CDIM; k0 += 16) {
        float4 av = *(const float4*)(Ap + k0);
        float4 bv = *(const float4*)(Wp + k0);
        __syncthreads();
        As[lc + 0][lr] = av.x; As[lc + 1][lr] = av.y;
        As[lc + 2][lr] = av.z; As[lc + 3][lr] = av.w;
        Bs[lc + 0][lr] = bv.x; Bs[lc + 1][lr] = bv.y;
        Bs[lc + 2][lr] = bv.z; Bs[lc + 3][lr] = bv.w;
        __syncthreads();
#pragma unroll
        for (int k = 0; k < 16; k++) {
            float4 a = *(const float4*)&As[k][ty << 2];
            float4 b = *(const float4*)&Bs[k][tx << 2];
            FMA16(a, b, acc)
        }
    }

    if (mode < 3) {
        float* OH = (mode == 0) ? g_Qh : ((mode == 1) ? g_Kh : g_Vh);
#pragma unroll
        for (int i = 0; i < 4; i++) {
            int row = r0 + (ty << 2) + i;
            int b = row >> 11, n = row & 2047;
#pragma unroll
            for (int j = 0; j < 4; j++) {
                int col = c0 + (tx << 2) + j;
                int h = col >> 6, d = col & 63;
                OH[(((b << 3) + h) * SEQ + n) * HDIM + d] = acc[i][j];
            }
        }
    } else {
#pragma unroll
        for (int i = 0; i < 4; i++) {
            int row = r0 + (ty << 2) + i;
            float4 o = make_float4(acc[i][0], acc[i][1], acc[i][2], acc[i][3]);
            *(float4*)&outPlain[(size_t)row * CDIM + c0 + (tx << 2)] = o;
        }
    }
}

// ---------------- S = (Qh @ Kh^T) * SCALE per (b,h) ----------------------
__global__ void qk_kernel()
{
    __shared__ float As[16][68];
    __shared__ float Bs[16][68];
    const int bh = blockIdx.z;
    const float* A = g_Qh + (size_t)bh * SEQ * HDIM;
    const float* Bm = g_Kh + (size_t)bh * SEQ * HDIM;
    float* Sp = g_S + (size_t)bh * SEQ * SEQ;
    const int tid = threadIdx.x;
    const int r0 = blockIdx.y << 6, c0 = blockIdx.x << 6;
    const int lr = tid >> 2;
    const int lc = (tid & 3) << 2;
    const float* Ap = A + (size_t)(r0 + lr) * HDIM + lc;
    const float* Kp = Bm + (size_t)(c0 + lr) * HDIM + lc;
    const int ty = tid >> 4, tx = tid & 15;
    float acc[4][4] = {};

#pragma unroll
    for (int k0 = 0; k0 < HDIM; k0 += 16) {
        float4 av = *(const float4*)(Ap + k0);
        float4 bv = *(const float4*)(Kp + k0);
        __syncthreads();
        As[lc + 0][lr] = av.x; As[lc + 1][lr] = av.y;
        As[lc + 2][lr] = av.z; As[lc + 3][lr] = av.w;
        Bs[lc + 0][lr] = bv.x; Bs[lc + 1][lr] = bv.y;
        Bs[lc + 2][lr] = bv.z; Bs[lc + 3][lr] = bv.w;
        __syncthreads();
#pragma unroll
        for (int k = 0; k < 16; k++) {
            float4 a = *(const float4*)&As[k][ty << 2];
            float4 b = *(const float4*)&Bs[k][tx << 2];
            FMA16(a, b, acc)
        }
    }
#pragma unroll
    for (int i = 0; i < 4; i++) {
        int row = r0 + (ty << 2) + i;
        float4 o = make_float4(acc[i][0] * QKSCALE, acc[i][1] * QKSCALE,
                               acc[i][2] * QKSCALE, acc[i][3] * QKSCALE);
        *(float4*)&Sp[(size_t)row * SEQ + c0 + (tx << 2)] = o;
    }
}

// ---------------- row argmax (q2k): argmax over m, first-occurrence ------
__global__ void row_argmax_kernel()
{
    int gw = (blockIdx.x * blockDim.x + threadIdx.x) >> 5;
    int lane = threadIdx.x & 31;
    int bh = gw >> 11, n = gw & 2047;
    const float* row = g_S + (size_t)bh * SEQ * SEQ + (size_t)n * SEQ;
    float best = -3e38f; int bi = 0x7fffffff;
#pragma unroll 8
    for (int m = lane; m < SEQ; m += 32) {
        float v = row[m];
        if (v > best) { best = v; bi = m; }
    }
#pragma unroll
    for (int o = 16; o; o >>= 1) {
        float ov = __shfl_xor_sync(0xffffffffu, best, o);
        int   oi = __shfl_xor_sync(0xffffffffu, bi, o);
        if (ov > best || (ov == best && oi < bi)) { best = ov; bi = oi; }
    }
    if (lane == 0) g_q2k[gw] = bi;
}

// ---------------- col argmax (k2q): argmax over n, first-occurrence ------
__global__ void col_argmax_kernel()
{
    __shared__ float sv[4][64];
    __shared__ int   si[4][64];
    int bh = blockIdx.y;
    int c = threadIdx.x & 63;
    int seg = threadIdx.x >> 6;
    int m = (blockIdx.x << 6) + c;
    const float* base = g_S + (size_t)bh * SEQ * SEQ + m;
    int n0 = seg << 9;
    float best = -3e38f; int bi = n0;
#pragma unroll 8
    for (int i = 0; i < 512; i++) {
        float v = base[(size_t)(n0 + i) << 11];
        if (v > best) { best = v; bi = n0 + i; }
    }
    sv[seg][c] = best; si[seg][c] = bi;
    __syncthreads();
    if (seg == 0) {
#pragma unroll
        for (int s2 = 1; s2 < 4; s2++) {
            float ov = sv[s2][c];
            if (ov > best) { best = ov; bi = si[s2][c]; }  // increasing n: keeps first
        }
        g_k2q[bh * SEQ + m] = bi;
    }
}

// ---------------- cycle consistency -> additive mask ---------------------
__global__ void asso_kernel(const int* __restrict__ smask,
                            const float* __restrict__ svalid)
{
    int i = blockIdx.x * blockDim.x + threadIdx.x;   // NBH*SEQ
    int bh = i >> 11, m = i & 2047;
    int b = bh >> 3;
    int kq = g_k2q[i];
    int remap = g_q2k[(bh << 11) + kq];
    float valid = (smask[(b << 11) + m] == smask[(b << 11) + remap])
                      ? svalid[(b << 11) + m] : 1.0f;
    g_madd[i] = valid * -10000.0f;
}

// ---------------- per-row softmax stats (max, 1/sum) ---------------------
__global__ void row_stats_kernel()
{
    int gw = (blockIdx.x * blockDim.x + threadIdx.x) >> 5;
    int lane = threadIdx.x & 31;
    int bh = gw >> 11, n = gw & 2047;
    const float* row = g_S + (size_t)bh * SEQ * SEQ + (size_t)n * SEQ;
    const float* ma = g_madd + bh * SEQ;
    float mx = -3e38f;
#pragma unroll 8
    for (int m = lane; m < SEQ; m += 32) mx = fmaxf(mx, row[m] + ma[m]);
#pragma unroll
    for (int o = 16; o; o >>= 1) mx = fmaxf(mx, __shfl_xor_sync(0xffffffffu, mx, o));
    float sum = 0.f;
#pragma unroll 8
    for (int m = lane; m < SEQ; m += 32) sum += fexp(row[m] + ma[m] - mx);
#pragma unroll
    for (int o = 16; o; o >>= 1) sum += __shfl_xor_sync(0xffffffffu, sum, o);
    if (lane == 0) { g_rmax[gw] = mx; g_rinv[gw] = 1.0f / sum; }
}

// ---------------- fused exp + P@V GEMM, writes X [B,N,C] layout ----------
__global__ void av_kernel()
{
    __shared__ float Ps[16][68];
    __shared__ float Vs[16][68];
    __shared__ float s_rmax[64];
    __shared__ float s_rinv[64];
    const int bh = blockIdx.y;
    const int n0 = blockIdx.x << 6;
    const int b = bh >> 3, h = bh & 7;
    const float* Sp = g_S + (size_t)bh * SEQ * SEQ;
    const float* Vp = g_Vh + (size_t)bh * SEQ * HDIM;
    const float* ma = g_madd + bh * SEQ;
    const int tid = threadIdx.x;
    const int lr = tid >> 2;
    const int lc = (tid & 3) << 2;
    const int vr = tid >> 4, vc = (tid & 15) << 2;
    const int ty = tid >> 4, tx = tid & 15;

    if (tid < 64) {
        s_rmax[tid] = g_rmax[bh * SEQ + n0 + tid];
        s_rinv[tid] = g_rinv[bh * SEQ + n0 + tid];
    }
    __syncthreads();
    const float rowmax_l = s_rmax[lr];
    float acc[4][4] = {};

    for (int m0 = 0; m0 < SEQ; m0 += 16) {
        float4 sv = *(const float4*)(Sp + (size_t)(n0 + lr) * SEQ + m0 + lc);
        float4 vv = *(const float4*)(Vp + (size_t)(m0 + vr) * HDIM + vc);
        float4 mv = *(const float4*)(ma + m0 + lc);
        __syncthreads();
        Ps[lc + 0][lr] = fexp(sv.x + mv.x - rowmax_l);
        Ps[lc + 1][lr] = fexp(sv.y + mv.y - rowmax_l);
        Ps[lc + 2][lr] = fexp(sv.z + mv.z - rowmax_l);
        Ps[lc + 3][lr] = fexp(sv.w + mv.w - rowmax_l);
        *(float4*)&Vs[vr][vc] = vv;
        __syncthreads();
#pragma unroll
        for (int k = 0; k < 16; k++) {
            float4 a = *(const float4*)&Ps[k][ty << 2];
            float4 bx = *(const float4*)&Vs[k][tx << 2];
            FMA16(a, bx, acc)
        }
    }
#pragma unroll
    for (int i = 0; i < 4; i++) {
        int n = n0 + (ty << 2) + i;
        float inv = s_rinv[(ty << 2) + i];
        float4 o = make_float4(acc[i][0] * inv, acc[i][1] * inv,
                               acc[i][2] * inv, acc[i][3] * inv);
        *(float4*)&g_X[(size_t)(b * SEQ + n) * CDIM + h * HDIM + (tx << 2)] = o;
    }
}

// ---------------- launcher ------------------------------------------------
extern "C" void kernel_launch(void* const* d_in, const int* in_sizes, int n_in,
                              void* d_out, int out_size)
{
    const float* q   = (const float*)d_in[0];
    const float* k   = (const float*)d_in[1];
    const float* v   = (const float*)d_in[2];
    const float* svm = (const float*)d_in[3];
    const int*   sm  = (const int*)d_in[4];
    const float* Wq  = (const float*)d_in[5];
    const float* Wk  = (const float*)d_in[6];
    const float* Wv  = (const float*)d_in[7];
    const float* Wp  = (const float*)d_in[8];
    float* out = (float*)d_out;

    float* X;
    cudaGetSymbolAddress((void**)&X, g_X);

    dim3 gp(CDIM / 64, (2 * SEQ) / 64);      // (8, 64)
    proj_kernel<<<gp, 256>>>(q, Wq, nullptr, 0);
    proj_kernel<<<gp, 256>>>(k, Wk, nullptr, 1);
    proj_kernel<<<gp, 256>>>(v, Wv, nullptr, 2);

    qk_kernel<<<dim3(SEQ / 64, SEQ / 64, NBH), 256>>>();

    row_argmax_kernel<<<(NBH * SEQ) / 8, 256>>>();
    col_argmax_kernel<<<dim3(SEQ / 64, NBH), 256>>>();
    asso_kernel<<<(NBH * SEQ) / 256, 256>>>(sm, svm);
    row_stats_kernel<<<(NBH * SEQ) / 8, 256>>>();

    av_kernel<<<dim3(SEQ / 64, NBH), 256>>>();

    proj_kernel<<<gp, 256>>>(X, Wp, out, 3);
}

// round 2
// speedup vs baseline: 1.1237x; 1.1237x over previous
#include <cuda_runtime.h>

#define SEQ   2048
#define HDIM  64
#define NHEAD 8
#define CDIM  512
#define NBH   16            // B*H
#define QKSCALE 0.125f

// ---------------- scratch (device globals; no allocation) ----------------
__device__ float g_Qh[NBH * SEQ * HDIM];
__device__ float g_Kh[NBH * SEQ * HDIM];
__device__ float g_Vh[NBH * SEQ * HDIM];
__device__ float g_S[(size_t)NBH * SEQ * SEQ];   // 268 MB
__device__ float g_X[2 * SEQ * CDIM];
__device__ int   g_q2k[NBH * SEQ];
__device__ int   g_k2q[NBH * SEQ];
__device__ float g_madd[NBH * SEQ];
// per-tile argmax partials: [bh][tile(32)][2048]
__device__ float g_rpv[NBH * 32 * SEQ];
__device__ int   g_rpi[NBH * 32 * SEQ];
__device__ float g_cpv[NBH * 32 * SEQ];
__device__ int   g_cpi[NBH * 32 * SEQ];

// fast exp on the FMA pipe (avoids MUFU throughput wall). |rel err| ~1e-7.
__device__ __forceinline__ float fexp(float x) {
    float y = x * 1.4426950408889634f;
    y = fminf(fmaxf(y, -126.0f), 126.0f);
    float t = y + 12582912.0f;                 // round-to-nearest magic
    int   e = __float_as_int(t) - 0x4B400000;  // integer part
    float r = t - 12582912.0f;
    float f = y - r;                           // f in [-0.5, 0.5]
    float p = 1.535336188319500e-4f;
    p = fmaf(p, f, 1.339887440266574e-3f);
    p = fmaf(p, f, 9.618437357674640e-3f);
    p = fmaf(p, f, 5.550332471162809e-2f);
    p = fmaf(p, f, 2.402264791363012e-1f);
    p = fmaf(p, f, 6.931472028550421e-1f);
    p = fmaf(p, f, 1.0f);
    return p * __int_as_float((e + 127) << 23);
}

#define FMA16(a, b, acc)                                                   \
    acc[0][0] = fmaf(a.x, b.x, acc[0][0]); acc[0][1] = fmaf(a.x, b.y, acc[0][1]); \
    acc[0][2] = fmaf(a.x, b.z, acc[0][2]); acc[0][3] = fmaf(a.x, b.w, acc[0][3]); \
    acc[1][0] = fmaf(a.y, b.x, acc[1][0]); acc[1][1] = fmaf(a.y, b.y, acc[1][1]); \
    acc[1][2] = fmaf(a.y, b.z, acc[1][2]); acc[1][3] = fmaf(a.y, b.w, acc[1][3]); \
    acc[2][0] = fmaf(a.z, b.x, acc[2][0]); acc[2][1] = fmaf(a.z, b.y, acc[2][1]); \
    acc[2][2] = fmaf(a.z, b.z, acc[2][2]); acc[2][3] = fmaf(a.z, b.w, acc[2][3]); \
    acc[3][0] = fmaf(a.w, b.x, acc[3][0]); acc[3][1] = fmaf(a.w, b.y, acc[3][1]); \
    acc[3][2] = fmaf(a.w, b.z, acc[3][2]); acc[3][3] = fmaf(a.w, b.w, acc[3][3]);

// ---------------- projection GEMM: C = A @ W^T, M=4096, N=K=512 ----------
__global__ void proj_kernel(const float* __restrict__ A,
                            const float* __restrict__ W,
                            float* __restrict__ outPlain, int mode)
{
    __shared__ float As[16][68];
    __shared__ float Bs[16][68];
    const int tid = threadIdx.x;
    const int r0 = blockIdx.y << 6, c0 = blockIdx.x << 6;
    const int lr = tid >> 2;
    const int lc = (tid & 3) << 2;
    const float* Ap = A + (size_t)(r0 + lr) * CDIM + lc;
    const float* Wp = W + (size_t)(c0 + lr) * CDIM + lc;
    const int ty = tid >> 4, tx = tid & 15;
    float acc[4][4] = {};

    for (int k0 = 0; k0 < CDIM; k0 += 16) {
        float4 av = *(const float4*)(Ap + k0);
        float4 bv = *(const float4*)(Wp + k0);
        __syncthreads();
        As[lc + 0][lr] = av.x; As[lc + 1][lr] = av.y;
        As[lc + 2][lr] = av.z; As[lc + 3][lr] = av.w;
        Bs[lc + 0][lr] = bv.x; Bs[lc + 1][lr] = bv.y;
        Bs[lc + 2][lr] = bv.z; Bs[lc + 3][lr] = bv.w;
        __syncthreads();
#pragma unroll
        for (int k = 0; k < 16; k++) {
            float4 a = *(const float4*)&As[k][ty << 2];
            float4 b = *(const float4*)&Bs[k][tx << 2];
            FMA16(a, b, acc)
        }
    }

    if (mode < 3) {
        float* OH = (mode == 0) ? g_Qh : ((mode == 1) ? g_Kh : g_Vh);
#pragma unroll
        for (int i = 0; i < 4; i++) {
            int row = r0 + (ty << 2) + i;
            int b = row >> 11, n = row & 2047;
#pragma unroll
            for (int j = 0; j < 4; j++) {
                int col = c0 + (tx << 2) + j;
                int h = col >> 6, d = col & 63;
                OH[(((b << 3) + h) * SEQ + n) * HDIM + d] = acc[i][j];
            }
        }
    } else {
#pragma unroll
        for (int i = 0; i < 4; i++) {
            int row = r0 + (ty << 2) + i;
            float4 o = make_float4(acc[i][0], acc[i][1], acc[i][2], acc[i][3]);
            *(float4*)&outPlain[(size_t)row * CDIM + c0 + (tx << 2)] = o;
        }
    }
}

// ---- S = (Qh @ Kh^T)*SCALE per (b,h), fused per-tile row/col argmax -----
__global__ void qk_kernel()
{
    __shared__ float As[16][68];
    __shared__ float Bs[16][68];
    const int bh = blockIdx.z;
    const float* A = g_Qh + (size_t)bh * SEQ * HDIM;
    const float* Bm = g_Kh + (size_t)bh * SEQ * HDIM;
    float* Sp = g_S + (size_t)bh * SEQ * SEQ;
    const int tid = threadIdx.x;
    const int r0 = blockIdx.y << 6, c0 = blockIdx.x << 6;
    const int lr = tid >> 2;
    const int lc = (tid & 3) << 2;
    const float* Ap = A + (size_t)(r0 + lr) * HDIM + lc;
    const float* Kp = Bm + (size_t)(c0 + lr) * HDIM + lc;
    const int ty = tid >> 4, tx = tid & 15;
    float acc[4][4] = {};

#pragma unroll
    for (int k0 = 0; k0 < HDIM; k0 += 16) {
        float4 av = *(const float4*)(Ap + k0);
        float4 bv = *(const float4*)(Kp + k0);
        __syncthreads();
        As[lc + 0][lr] = av.x; As[lc + 1][lr] = av.y;
        As[lc + 2][lr] = av.z; As[lc + 3][lr] = av.w;
        Bs[lc + 0][lr] = bv.x; Bs[lc + 1][lr] = bv.y;
        Bs[lc + 2][lr] = bv.z; Bs[lc + 3][lr] = bv.w;
        __syncthreads();
#pragma unroll
        for (int k = 0; k < 16; k++) {
            float4 a = *(const float4*)&As[k][ty << 2];
            float4 b = *(const float4*)&Bs[k][tx << 2];
            FMA16(a, b, acc)
        }
    }

    // scale + store S tile
#pragma unroll
    for (int i = 0; i < 4; i++) {
#pragma unroll
        for (int j = 0; j < 4; j++) acc[i][j] *= QKSCALE;
        int row = r0 + (ty << 2) + i;
        float4 o = make_float4(acc[i][0], acc[i][1], acc[i][2], acc[i][3]);
        *(float4*)&Sp[(size_t)row * SEQ + c0 + (tx << 2)] = o;
    }

    // ---- row partial argmax (over this tile's 64 cols), first-occurrence
#pragma unroll
    for (int i = 0; i < 4; i++) {
        float v = acc[i][0]; int jj = 0;
        if (acc[i][1] > v) { v = acc[i][1]; jj = 1; }
        if (acc[i][2] > v) { v = acc[i][2]; jj = 2; }
        if (acc[i][3] > v) { v = acc[i][3]; jj = 3; }
        int idx = c0 + (tx << 2) + jj;
#pragma unroll
        for (int o = 1; o < 16; o <<= 1) {
            float ov = __shfl_xor_sync(0xffffffffu, v, o);
            int   oi = __shfl_xor_sync(0xffffffffu, idx, o);
            if (ov > v || (ov == v && oi < idx)) { v = ov; idx = oi; }
        }
        if (tx == 0) {
            int n = r0 + (ty << 2) + i;
            size_t p = (size_t)((bh << 5) + (c0 >> 6)) * SEQ + n;
            g_rpv[p] = v; g_rpi[p] = idx;
        }
    }

    // ---- col partial argmax (over this tile's 64 rows), reuse smem ------
    __syncthreads();
    float* cv = &As[0][0];
    int*   ci = (int*)&Bs[0][0];
#pragma unroll
    for (int j = 0; j < 4; j++) {
        float v = acc[0][j]; int ii = 0;
        if (acc[1][j] > v) { v = acc[1][j]; ii = 1; }
        if (acc[2][j] > v) { v = acc[2][j]; ii = 2; }
        if (acc[3][j] > v) { v = acc[3][j]; ii = 3; }
        cv[ty * 64 + (tx << 2) + j] = v;
        ci[ty * 64 + (tx << 2) + j] = r0 + (ty << 2) + ii;
    }
    __syncthreads();
    if (tid < 64) {
        float v = cv[tid]; int idx = ci[tid];
#pragma unroll
        for (int t = 1; t < 16; t++) {
            float ov = cv[t * 64 + tid];
            if (ov > v) { v = ov; idx = ci[t * 64 + tid]; }  // asc rows: first kept
        }
        size_t p = (size_t)((bh << 5) + (r0 >> 6)) * SEQ + c0 + tid;
        g_cpv[p] = v; g_cpi[p] = idx;
    }
}

// ---------------- reduce 32 partials -> q2k and k2q ----------------------
__global__ void argmax_reduce_kernel()
{
    int gid = blockIdx.x * blockDim.x + threadIdx.x;   // 2*NBH*SEQ
    int which = gid >= NBH * SEQ;                      // 0: row(q2k), 1: col(k2q)
    int i = gid & (NBH * SEQ - 1);
    int bh = i >> 11, n = i & 2047;
    const float* pv = which ? g_cpv : g_rpv;
    const int*   pi = which ? g_cpi : g_rpi;
    float v = -3e38f; int idx = 0;
#pragma unroll 8
    for (int t = 0; t < 32; t++) {
        size_t p = (size_t)((bh << 5) + t) * SEQ + n;
        float ov = pv[p];
        if (ov > v) { v = ov; idx = pi[p]; }   // ascending tile: first kept
    }
    (which ? g_k2q : g_q2k)[i] = idx;
}

// ---------------- cycle consistency -> additive mask ---------------------
__global__ void asso_kernel(const int* __restrict__ smask,
                            const float* __restrict__ svalid)
{
    int i = blockIdx.x * blockDim.x + threadIdx.x;   // NBH*SEQ
    int bh = i >> 11, m = i & 2047;
    int b = bh >> 3;
    int kq = g_k2q[i];
    int remap = g_q2k[(bh << 11) + kq];
    float valid = (smask[(b << 11) + m] == smask[(b << 11) + remap])
                      ? svalid[(b << 11) + m] : 1.0f;
    g_madd[i] = valid * -10000.0f;
}

// ---- fused exp + online row-sum + P@V GEMM, writes X [B,N,C] layout -----
// No max subtraction needed: |S| is small and bounded; masked entries
// (s-10000) underflow to ~2^-126 ~ 0 in fexp. Rows are never fully masked
// in fp terms that matter (sum of unmasked exps >> 2048*2^-126).
__global__ void av_kernel()
{
    __shared__ float Ps[16][68];
    __shared__ float Vs[16][68];
    __shared__ float sL[64];
    const int bh = blockIdx.y;
    const int n0 = blockIdx.x << 6;
    const int b = bh >> 3, h = bh & 7;
    const float* Sp = g_S + (size_t)bh * SEQ * SEQ;
    const float* Vp = g_Vh + (size_t)bh * SEQ * HDIM;
    const float* ma = g_madd + bh * SEQ;
    const int tid = threadIdx.x;
    const int lr = tid >> 2;
    const int lc = (tid & 3) << 2;
    const int vr = tid >> 4, vc = (tid & 15) << 2;
    const int ty = tid >> 4, tx = tid & 15;

    float runL = 0.0f;
    float acc[4][4] = {};

    for (int m0 = 0; m0 < SEQ; m0 += 16) {
        float4 sv = *(const float4*)(Sp + (size_t)(n0 + lr) * SEQ + m0 + lc);
        float4 vv = *(const float4*)(Vp + (size_t)(m0 + vr) * HDIM + vc);
        float4 mv = *(const float4*)(ma + m0 + lc);
        __syncthreads();
        float p0 = fexp(sv.x + mv.x);
        float p1 = fexp(sv.y + mv.y);
        float p2 = fexp(sv.z + mv.z);
        float p3 = fexp(sv.w + mv.w);
        Ps[lc + 0][lr] = p0; Ps[lc + 1][lr] = p1;
        Ps[lc + 2][lr] = p2; Ps[lc + 3][lr] = p3;
        runL += (p0 + p1) + (p2 + p3);
        *(float4*)&Vs[vr][vc] = vv;
        __syncthreads();
#pragma unroll
        for (int k = 0; k < 16; k++) {
            float4 a = *(const float4*)&Ps[k][ty << 2];
            float4 bx = *(const float4*)&Vs[k][tx << 2];
            FMA16(a, bx, acc)
        }
    }
    // total row sum: reduce the 4 lanes sharing row lr
    runL += __shfl_xor_sync(0xffffffffu, runL, 1);
    runL += __shfl_xor_sync(0xffffffffu, runL, 2);
    if ((tid & 3) == 0) sL[lr] = runL;
    __syncthreads();
#pragma unroll
    for (int i = 0; i < 4; i++) {
        int n = n0 + (ty << 2) + i;
        float inv = 1.0f / sL[(ty << 2) + i];
        float4 o = make_float4(acc[i][0] * inv, acc[i][1] * inv,
                               acc[i][2] * inv, acc[i][3] * inv);
        *(float4*)&g_X[(size_t)(b * SEQ + n) * CDIM + h * HDIM + (tx << 2)] = o;
    }
}

// ---------------- launcher ------------------------------------------------
extern "C" void kernel_launch(void* const* d_in, const int* in_sizes, int n_in,
                              void* d_out, int out_size)
{
    const float* q   = (const float*)d_in[0];
    const float* k   = (const float*)d_in[1];
    const float* v   = (const float*)d_in[2];
    const float* svm = (const float*)d_in[3];
    const int*   sm  = (const int*)d_in[4];
    const float* Wq  = (const float*)d_in[5];
    const float* Wk  = (const float*)d_in[6];
    const float* Wv  = (const float*)d_in[7];
    const float* Wp  = (const float*)d_in[8];
    float* out = (float*)d_out;

    float* X;
    cudaGetSymbolAddress((void**)&X, g_X);

    dim3 gp(CDIM / 64, (2 * SEQ) / 64);      // (8, 64)
    proj_kernel<<<gp, 256>>>(q, Wq, nullptr, 0);
    proj_kernel<<<gp, 256>>>(k, Wk, nullptr, 1);
    proj_kernel<<<gp, 256>>>(v, Wv, nullptr, 2);

    qk_kernel<<<dim3(SEQ / 64, SEQ / 64, NBH), 256>>>();

    argmax_reduce_kernel<<<(2 * NBH * SEQ) / 256, 256>>>();
    asso_kernel<<<(NBH * SEQ) / 256, 256>>>(sm, svm);

    av_kernel<<<dim3(SEQ / 64, NBH), 256>>>();

    proj_kernel<<<gp, 256>>>(X, Wp, out, 3);
}

// round 4
// speedup vs baseline: 1.1980x; 1.0661x over previous
#include <cuda_runtime.h>
#include <cuda_bf16.h>
#include <cstdint>

#define SEQ   2048
#define HDIM  64
#define NHEAD 8
#define CDIM  512
#define NBH   16            // B*H
#define QKSCALE 0.125f
#define KP    24            // smem tile pitch in halfs (48B, ldmatrix conflict-free)
#define PLANE (64 * KP)     // halfs per 64x16 padded tile

constexpr int NQe = NBH * SEQ * HDIM;   // 2,097,152 elements per plane

// ---------------- scratch (device globals; no allocation) ----------------
__device__ float g_Qh[NBH * SEQ * HDIM];          // fp32 proj outputs
__device__ float g_Kh[NBH * SEQ * HDIM];
__device__ float g_Vt[NBH * HDIM * SEQ];          // V transposed [bh][d][s]
__device__ __nv_bfloat16 g_Qh3[3 * NBH * SEQ * HDIM];  // hi/mid/lo planes
__device__ __nv_bfloat16 g_Kh3[3 * NBH * SEQ * HDIM];
__device__ __nv_bfloat16 g_Vt2[2 * NBH * HDIM * SEQ];  // hi/lo planes
__device__ float g_S[(size_t)NBH * SEQ * SEQ];    // 268 MB
__device__ float g_X[2 * SEQ * CDIM];
__device__ int   g_q2k[NBH * SEQ];
__device__ int   g_k2q[NBH * SEQ];
__device__ float g_madd[NBH * SEQ];
__device__ float g_rpv[NBH * 32 * SEQ];
__device__ int   g_rpi[NBH * 32 * SEQ];
__device__ float g_cpv[NBH * 32 * SEQ];
__device__ int   g_cpi[NBH * 32 * SEQ];

// fast exp on the FMA pipe. |rel err| ~1e-7.
__device__ __forceinline__ float fexp(float x) {
    float y = x * 1.4426950408889634f;
    y = fminf(fmaxf(y, -126.0f), 126.0f);
    float t = y + 12582912.0f;
    int   e = __float_as_int(t) - 0x4B400000;
    float r = t - 12582912.0f;
    float f = y - r;
    float p = 1.535336188319500e-4f;
    p = fmaf(p, f, 1.339887440266574e-3f);
    p = fmaf(p, f, 9.618437357674640e-3f);
    p = fmaf(p, f, 5.550332471162809e-2f);
    p = fmaf(p, f, 2.402264791363012e-1f);
    p = fmaf(p, f, 6.931472028550421e-1f);
    p = fmaf(p, f, 1.0f);
    return p * __int_as_float((e + 127) << 23);
}

#define MMA_BF16(d, a, b0, b1)                                              \
    asm volatile("mma.sync.aligned.m16n8k16.row.col.f32.bf16.bf16.f32 "      \
                 "{%0,%1,%2,%3}, {%4,%5,%6,%7}, {%8,%9}, {%0,%1,%2,%3};"     \
                 : "+f"((d)[0]), "+f"((d)[1]), "+f"((d)[2]), "+f"((d)[3])    \
                 : "r"((a)[0]), "r"((a)[1]), "r"((a)[2]), "r"((a)[3]),       \
                   "r"(b0), "r"(b1))

#define LDM4(r, addr)                                                        \
    asm volatile("ldmatrix.sync.aligned.m8n8.x4.shared.b16 {%0,%1,%2,%3}, [%4];" \
                 : "=r"((r)[0]), "=r"((r)[1]), "=r"((r)[2]), "=r"((r)[3])    \
                 : "r"(addr))

__device__ __forceinline__ uint32_t pack_bf2(float a, float b) {
    __nv_bfloat162 t;
    t.x = __float2bfloat16_rn(a);
    t.y = __float2bfloat16_rn(b);
    return *(uint32_t*)&t;
}

#define FMA16(a, b, acc)                                                   \
    acc[0][0] = fmaf(a.x, b.x, acc[0][0]); acc[0][1] = fmaf(a.x, b.y, acc[0][1]); \
    acc[0][2] = fmaf(a.x, b.z, acc[0][2]); acc[0][3] = fmaf(a.x, b.w, acc[0][3]); \
    acc[1][0] = fmaf(a.y, b.x, acc[1][0]); acc[1][1] = fmaf(a.y, b.y, acc[1][1]); \
    acc[1][2] = fmaf(a.y, b.z, acc[1][2]); acc[1][3] = fmaf(a.y, b.w, acc[1][3]); \
    acc[2][0] = fmaf(a.z, b.x, acc[2][0]); acc[2][1] = fmaf(a.z, b.y, acc[2][1]); \
    acc[2][2] = fmaf(a.z, b.z, acc[2][2]); acc[2][3] = fmaf(a.z, b.w, acc[2][3]); \
    acc[3][0] = fmaf(a.w, b.x, acc[3][0]); acc[3][1] = fmaf(a.w, b.y, acc[3][1]); \
    acc[3][2] = fmaf(a.w, b.z, acc[3][2]); acc[3][3] = fmaf(a.w, b.w, acc[3][3]);

// ---------------- projection GEMM (FFMA, unchanged core) -----------------
__global__ void proj_kernel(const float* __restrict__ A,
                            const float* __restrict__ W,
                            float* __restrict__ outPlain, int mode)
{
    __shared__ float As[16][68];
    __shared__ float Bs[16][68];
    const int tid = threadIdx.x;
    const int r0 = blockIdx.y << 6, c0 = blockIdx.x << 6;
    const int lr = tid >> 2;
    const int lc = (tid & 3) << 2;
    const float* Ap = A + (size_t)(r0 + lr) * CDIM + lc;
    const float* Wp = W + (size_t)(c0 + lr) * CDIM + lc;
    const int ty = tid >> 4, tx = tid & 15;
    float acc[4][4] = {};

    for (int k0 = 0; k0 < CDIM; k0 += 16) {
        float4 av = *(const float4*)(Ap + k0);
        float4 bv = *(const float4*)(Wp + k0);
        __syncthreads();
        As[lc + 0][lr] = av.x; As[lc + 1][lr] = av.y;
        As[lc + 2][lr] = av.z; As[lc + 3][lr] = av.w;
        Bs[lc + 0][lr] = bv.x; Bs[lc + 1][lr] = bv.y;
        Bs[lc + 2][lr] = bv.z; Bs[lc + 3][lr] = bv.w;
        __syncthreads();
#pragma unroll
        for (int k = 0; k < 16; k++) {
            float4 a = *(const float4*)&As[k][ty << 2];
            float4 b = *(const float4*)&Bs[k][tx << 2];
            FMA16(a, b, acc)
        }
    }

    if (mode == 2) {
#pragma unroll
        for (int i = 0; i < 4; i++) {
            int row = r0 + (ty << 2) + i;
            int b = row >> 11, n = row & 2047;
#pragma unroll
            for (int j = 0; j < 4; j++) {
                int col = c0 + (tx << 2) + j;
                int h = col >> 6, d = col & 63;
                g_Vt[(size_t)(((b << 3) + h) * HDIM + d) * SEQ + n] = acc[i][j];
            }
        }
    } else if (mode < 2) {
        float* OH = (mode == 0) ? g_Qh : g_Kh;
#pragma unroll
        for (int i = 0; i < 4; i++) {
            int row = r0 + (ty << 2) + i;
            int b = row >> 11, n = row & 2047;
#pragma unroll
            for (int j = 0; j < 4; j++) {
                int col = c0 + (tx << 2) + j;
                int h = col >> 6, d = col & 63;
                OH[(((b << 3) + h) * SEQ + n) * HDIM + d] = acc[i][j];
            }
        }
    } else {
#pragma unroll
        for (int i = 0; i < 4; i++) {
            int row = r0 + (ty << 2) + i;
            float4 o = make_float4(acc[i][0], acc[i][1], acc[i][2], acc[i][3]);
            *(float4*)&outPlain[(size_t)row * CDIM + c0 + (tx << 2)] = o;
        }
    }
}

// ---------------- fp32 -> bf16 split planes (2 or 3) ---------------------
__global__ void cvt_split_kernel(const float* __restrict__ in,
                                 __nv_bfloat16* __restrict__ out,
                                 int n, int three)
{
    int i = blockIdx.x * blockDim.x + threadIdx.x;
    if (i >= n) return;
    float x = in[i];
    __nv_bfloat16 h = __float2bfloat16_rn(x);
    float r1 = x - __bfloat162float(h);
    __nv_bfloat16 m = __float2bfloat16_rn(r1);
    out[i] = h;
    out[n + i] = m;
    if (three) {
        float r2 = r1 - __bfloat162float(m);
        out[2 * n + i] = __float2bfloat16_rn(r2);
    }
}

// ---- S = (Qh @ Kh^T)*SCALE via bf16 split-3 MMA + fused tile argmax -----
__global__ void __launch_bounds__(128) qk_mma_kernel()
{
    __shared__ __align__(16) unsigned char smraw[6 * PLANE * 2];  // 18432 B
    __nv_bfloat16* sAB = (__nv_bfloat16*)smraw;
    float* Ssm = (float*)smraw;                                   // 64x68 fp32 epilogue

    const int bh = blockIdx.z;
    const int r0 = blockIdx.y << 6, c0 = blockIdx.x << 6;
    const int tid = threadIdx.x, lane = tid & 31, w = tid >> 5;
    const int wm = (w & 1) << 5, wn = (w >> 1) << 5;

    const size_t qoff = (size_t)bh * SEQ * HDIM + (size_t)(r0 + (tid >> 1)) * HDIM + (tid & 1) * 8;
    const size_t koff = (size_t)bh * SEQ * HDIM + (size_t)(c0 + (tid >> 1)) * HDIM + (tid & 1) * 8;
    const __nv_bfloat16* qp[3] = { g_Qh3 + qoff, g_Qh3 + (size_t)NQe + qoff, g_Qh3 + 2 * (size_t)NQe + qoff };
    const __nv_bfloat16* kp[3] = { g_Kh3 + koff, g_Kh3 + (size_t)NQe + koff, g_Kh3 + 2 * (size_t)NQe + koff };
    const int sts = (tid >> 1) * KP + (tid & 1) * 8;

    uint32_t sbase = (uint32_t)__cvta_generic_to_shared(sAB);
    const int lrow = (lane & 7) + ((lane >> 3) & 1) * 8;
    const int lk = (lane >> 4) * 8;
    uint32_t adA[3][2], adB[3][2];
#pragma unroll
    for (int p = 0; p < 3; p++)
#pragma unroll
        for (int t = 0; t < 2; t++) {
            adA[p][t] = sbase + 2 * (p * PLANE + (wm + 16 * t + lrow) * KP + lk);
            adB[p][t] = sbase + 2 * ((3 + p) * PLANE + (wn + 16 * t + lrow) * KP + lk);
        }

    float acc[2][4][4] = {};

#pragma unroll 1
    for (int ks = 0; ks < 4; ks++) {
        uint4 qv[3], kv[3];
#pragma unroll
        for (int p = 0; p < 3; p++) {
            qv[p] = *(const uint4*)(qp[p] + ks * 16);
            kv[p] = *(const uint4*)(kp[p] + ks * 16);
        }
        __syncthreads();
#pragma unroll
        for (int p = 0; p < 3; p++) {
            *(uint4*)&sAB[p * PLANE + sts] = qv[p];
            *(uint4*)&sAB[(3 + p) * PLANE + sts] = kv[p];
        }
        __syncthreads();

        uint32_t afr[3][2][4], bfr[3][2][4];
#pragma unroll
        for (int p = 0; p < 3; p++)
#pragma unroll
            for (int t = 0; t < 2; t++) { LDM4(afr[p][t], adA[p][t]); LDM4(bfr[p][t], adB[p][t]); }

        // split-3 combos: hh, hm, mh, mm, hl, lh
        const int pa[6] = {0, 0, 1, 1, 0, 2};
        const int pb[6] = {0, 1, 0, 1, 2, 0};
#pragma unroll
        for (int c = 0; c < 6; c++)
#pragma unroll
            for (int mt = 0; mt < 2; mt++)
#pragma unroll
                for (int nt = 0; nt < 4; nt++) {
                    int n2 = nt >> 1, j = nt & 1;
                    MMA_BF16(acc[mt][nt], afr[pa[c]][mt], bfr[pb[c]][n2][j], bfr[pb[c]][n2][j + 2]);
                }
    }

    __syncthreads();
#pragma unroll
    for (int mt = 0; mt < 2; mt++) {
        int row0 = wm + 16 * mt + (lane >> 2);
#pragma unroll
        for (int nt = 0; nt < 4; nt++) {
            int col = wn + 8 * nt + 2 * (lane & 3);
            *(float2*)&Ssm[row0 * 68 + col] =
                make_float2(acc[mt][nt][0] * QKSCALE, acc[mt][nt][1] * QKSCALE);
            *(float2*)&Ssm[(row0 + 8) * 68 + col] =
                make_float2(acc[mt][nt][2] * QKSCALE, acc[mt][nt][3] * QKSCALE);
        }
    }
    __syncthreads();

    float* Sp = g_S + (size_t)bh * SEQ * SEQ;
    {
        int row = tid >> 1, cb = (tid & 1) * 32;
#pragma unroll
        for (int i = 0; i < 8; i++)
            *(float4*)&Sp[(size_t)(r0 + row) * SEQ + c0 + cb + 4 * i] =
                *(const float4*)&Ssm[row * 68 + cb + 4 * i];
    }

    if (tid < 64) {
        float best = -3e38f; int bi = 0;
#pragma unroll
        for (int i = 0; i < 16; i++) {
            float4 v = *(const float4*)&Ssm[tid * 68 + 4 * i];
            if (v.x > best) { best = v.x; bi = 4 * i; }
            if (v.y > best) { best = v.y; bi = 4 * i + 1; }
            if (v.z > best) { best = v.z; bi = 4 * i + 2; }
            if (v.w > best) { best = v.w; bi = 4 * i + 3; }
        }
        size_t p = (size_t)((bh << 5) + blockIdx.x) * SEQ + r0 + tid;
        g_rpv[p] = best; g_rpi[p] = c0 + bi;
    } else {
        int c = tid - 64;
        float best = -3e38f; int bi = 0;
#pragma unroll 8
        for (int i = 0; i < 64; i++) {
            float v = Ssm[i * 68 + c];
            if (v > best) { best = v; bi = i; }
        }
        size_t p = (size_t)((bh << 5) + blockIdx.y) * SEQ + c0 + c;
        g_cpv[p] = best; g_cpi[p] = r0 + bi;
    }
}

// ---------------- reduce 32 partials -> q2k and k2q ----------------------
__global__ void argmax_reduce_kernel()
{
    int gid = blockIdx.x * blockDim.x + threadIdx.x;
    int which = gid >= NBH * SEQ;
    int i = gid & (NBH * SEQ - 1);
    int bh = i >> 11, n = i & 2047;
    const float* pv = which ? g_cpv : g_rpv;
    const int*   pi = which ? g_cpi : g_rpi;
    float v = -3e38f; int idx = 0;
#pragma unroll 8
    for (int t = 0; t < 32; t++) {
        size_t p = (size_t)((bh << 5) + t) * SEQ + n;
        float ov = pv[p];
        if (ov > v) { v = ov; idx = pi[p]; }
    }
    (which ? g_k2q : g_q2k)[i] = idx;
}

// ---------------- cycle consistency -> additive mask ---------------------
__global__ void asso_kernel(const int* __restrict__ smask,
                            const float* __restrict__ svalid)
{
    int i = blockIdx.x * blockDim.x + threadIdx.x;
    int bh = i >> 11, m = i & 2047;
    int b = bh >> 3;
    int kq = g_k2q[i];
    int remap = g_q2k[(bh << 11) + kq];
    float valid = (smask[(b << 11) + m] == smask[(b << 11) + remap])
                      ? svalid[(b << 11) + m] : 1.0f;
    g_madd[i] = valid * -10000.0f;
}

// ---- fused exp + online row-sum + P@V via bf16 split-2 MMA --------------
__global__ void __launch_bounds__(128) av_mma_kernel()
{
    __shared__ __align__(16) __nv_bfloat16 sAB[4 * PLANE];  // Ph,Pl,Vh,Vl
    __shared__ float sL[64];

    const int bh = blockIdx.y;
    const int n0 = blockIdx.x << 6;
    const int b = bh >> 3, h = bh & 7;
    const int tid = threadIdx.x, lane = tid & 31, w = tid >> 5;
    const int wm = (w & 1) << 5, wn = (w >> 1) << 5;

    const float* Sp = g_S + (size_t)bh * SEQ * SEQ + (size_t)(n0 + (tid >> 1)) * SEQ + (tid & 1) * 8;
    const float* mp = g_madd + bh * SEQ + (tid & 1) * 8;
    const size_t voff = (size_t)bh * HDIM * SEQ + (size_t)(tid >> 1) * SEQ + (tid & 1) * 8;
    const __nv_bfloat16* vp[2] = { g_Vt2 + voff, g_Vt2 + (size_t)NQe + voff };
    const int sts = (tid >> 1) * KP + (tid & 1) * 8;

    uint32_t sbase = (uint32_t)__cvta_generic_to_shared(sAB);
    const int lrow = (lane & 7) + ((lane >> 3) & 1) * 8;
    const int lk = (lane >> 4) * 8;
    uint32_t adA[2][2], adB[2][2];
#pragma unroll
    for (int p = 0; p < 2; p++)
#pragma unroll
        for (int t = 0; t < 2; t++) {
            adA[p][t] = sbase + 2 * (p * PLANE + (wm + 16 * t + lrow) * KP + lk);
            adB[p][t] = sbase + 2 * ((2 + p) * PLANE + (wn + 16 * t + lrow) * KP + lk);
        }

    float acc[2][4][4] = {};
    float runL = 0.0f;

#pragma unroll 1
    for (int ks = 0; ks < 128; ks++) {
        float4 s0 = *(const float4*)(Sp + ks * 16);
        float4 s1 = *(const float4*)(Sp + ks * 16 + 4);
        float4 m0 = *(const float4*)(mp + ks * 16);
        float4 m1 = *(const float4*)(mp + ks * 16 + 4);
        uint4 v0 = *(const uint4*)(vp[0] + ks * 16);
        uint4 v1 = *(const uint4*)(vp[1] + ks * 16);

        float pv[8];
        pv[0] = fexp(s0.x + m0.x); pv[1] = fexp(s0.y + m0.y);
        pv[2] = fexp(s0.z + m0.z); pv[3] = fexp(s0.w + m0.w);
        pv[4] = fexp(s1.x + m1.x); pv[5] = fexp(s1.y + m1.y);
        pv[6] = fexp(s1.z + m1.z); pv[7] = fexp(s1.w + m1.w);
        runL += ((pv[0] + pv[1]) + (pv[2] + pv[3])) + ((pv[4] + pv[5]) + (pv[6] + pv[7]));

        uint4 ph, pl;
        float hs[8];
#pragma unroll
        for (int i = 0; i < 8; i++)
            hs[i] = __bfloat162float(__float2bfloat16_rn(pv[i]));
        ph.x = pack_bf2(pv[0], pv[1]); ph.y = pack_bf2(pv[2], pv[3]);
        ph.z = pack_bf2(pv[4], pv[5]); ph.w = pack_bf2(pv[6], pv[7]);
        pl.x = pack_bf2(pv[0] - hs[0], pv[1] - hs[1]);
        pl.y = pack_bf2(pv[2] - hs[2], pv[3] - hs[3]);
        pl.z = pack_bf2(pv[4] - hs[4], pv[5] - hs[5]);
        pl.w = pack_bf2(pv[6] - hs[6], pv[7] - hs[7]);

        __syncthreads();
        *(uint4*)&sAB[0 * PLANE + sts] = ph;
        *(uint4*)&sAB[1 * PLANE + sts] = pl;
        *(uint4*)&sAB[2 * PLANE + sts] = v0;
        *(uint4*)&sAB[3 * PLANE + sts] = v1;
        __syncthreads();

        uint32_t afr[2][2][4], bfr[2][2][4];
#pragma unroll
        for (int p = 0; p < 2; p++)
#pragma unroll
            for (int t = 0; t < 2; t++) { LDM4(afr[p][t], adA[p][t]); LDM4(bfr[p][t], adB[p][t]); }

        // split-2 combos: hh, hl, lh
        const int pa[3] = {0, 0, 1};
        const int pb[3] = {0, 1, 0};
#pragma unroll
        for (int c = 0; c < 3; c++)
#pragma unroll
            for (int mt = 0; mt < 2; mt++)
#pragma unroll
                for (int nt = 0; nt < 4; nt++) {
                    int n2 = nt >> 1, j = nt & 1;
                    MMA_BF16(acc[mt][nt], afr[pa[c]][mt], bfr[pb[c]][n2][j], bfr[pb[c]][n2][j + 2]);
                }
    }

    runL += __shfl_xor_sync(0xffffffffu, runL, 1);
    if (!(tid & 1)) sL[tid >> 1] = runL;
    __syncthreads();

#pragma unroll
    for (int mt = 0; mt < 2; mt++) {
        int row0 = wm + 16 * mt + (lane >> 2);
        float inv0 = 1.0f / sL[row0];
        float inv1 = 1.0f / sL[row0 + 8];
#pragma unroll
        for (int nt = 0; nt < 4; nt++) {
            int col = wn + 8 * nt + 2 * (lane & 3);
            int n = n0 + row0;
            *(float2*)&g_X[(size_t)(b * SEQ + n) * CDIM + h * HDIM + col] =
                make_float2(acc[mt][nt][0] * inv0, acc[mt][nt][1] * inv0);
            *(float2*)&g_X[(size_t)(b * SEQ + n + 8) * CDIM + h * HDIM + col] =
                make_float2(acc[mt][nt][2] * inv1, acc[mt][nt][3] * inv1);
        }
    }
}

// ---------------- launcher ------------------------------------------------
extern "C" void kernel_launch(void* const* d_in, const int* in_sizes, int n_in,
                              void* d_out, int out_size)
{
    const float* q   = (const float*)d_in[0];
    const float* k   = (const float*)d_in[1];
    const float* v   = (const float*)d_in[2];
    const float* svm = (const float*)d_in[3];
    const int*   sm  = (const int*)d_in[4];
    const float* Wq  = (const float*)d_in[5];
    const float* Wk  = (const float*)d_in[6];
    const float* Wv  = (const float*)d_in[7];
    const float* Wp  = (const float*)d_in[8];
    float* out = (float*)d_out;

    float *X, *QhF, *KhF, *VtF;
    __nv_bfloat16 *Q3, *K3, *V2;
    cudaGetSymbolAddress((void**)&X, g_X);
    cudaGetSymbolAddress((void**)&QhF, g_Qh);
    cudaGetSymbolAddress((void**)&KhF, g_Kh);
    cudaGetSymbolAddress((void**)&VtF, g_Vt);
    cudaGetSymbolAddress((void**)&Q3, g_Qh3);
    cudaGetSymbolAddress((void**)&K3, g_Kh3);
    cudaGetSymbolAddress((void**)&V2, g_Vt2);

    dim3 gp(CDIM / 64, (2 * SEQ) / 64);      // (8, 64)
    proj_kernel<<<gp, 256>>>(q, Wq, nullptr, 0);
    proj_kernel<<<gp, 256>>>(k, Wk, nullptr, 1);
    proj_kernel<<<gp, 256>>>(v, Wv, nullptr, 2);

    int cvtb = NQe / 256;
    cvt_split_kernel<<<cvtb, 256>>>(QhF, Q3, NQe, 1);
    cvt_split_kernel<<<cvtb, 256>>>(KhF, K3, NQe, 1);
    cvt_split_kernel<<<cvtb, 256>>>(VtF, V2, NQe, 0);

    qk_mma_kernel<<<dim3(SEQ / 64, SEQ / 64, NBH), 128>>>();

    argmax_reduce_kernel<<<(2 * NBH * SEQ) / 256, 256>>>();
    asso_kernel<<<(NBH * SEQ) / 256, 256>>>(sm, svm);

    av_mma_kernel<<<dim3(SEQ / 64, NBH), 128>>>();

    proj_kernel<<<gp, 256>>>(X, Wp, out, 3);
}

// round 6
// speedup vs baseline: 1.2944x; 1.0805x over previous
#include <cuda_runtime.h>
#include <cuda_bf16.h>
#include <cuda_fp16.h>
#include <cstdint>

#define SEQ   2048
#define HDIM  64
#define NHEAD 8
#define CDIM  512
#define NBH   16            // B*H
#define QKSCALE 0.125f
#define KP    24            // smem tile pitch in halfs (48B, ldmatrix conflict-free)
#define PLANE (64 * KP)     // halfs per 64x16 padded tile

constexpr int NQe = NBH * SEQ * HDIM;   // 2,097,152 elements per plane

// ---------------- scratch (device globals; no allocation) ----------------
__device__ float g_Qh[NBH * SEQ * HDIM];          // fp32 proj outputs
__device__ float g_Kh[NBH * SEQ * HDIM];
__device__ float g_Vt[NBH * HDIM * SEQ];          // V transposed [bh][d][s]
__device__ __half g_Qh2[2 * NBH * SEQ * HDIM];    // hi/lo fp16 planes
__device__ __half g_Kh2[2 * NBH * SEQ * HDIM];
__device__ __half g_Vt2[2 * NBH * HDIM * SEQ];
__device__ float g_S[(size_t)NBH * SEQ * SEQ];    // 268 MB
__device__ float g_X[2 * SEQ * CDIM];
__device__ int   g_q2k[NBH * SEQ];
__device__ int   g_k2q[NBH * SEQ];
__device__ float g_madd[NBH * SEQ];
__device__ float g_rpv[NBH * 32 * SEQ];
__device__ int   g_rpi[NBH * 32 * SEQ];
__device__ float g_cpv[NBH * 32 * SEQ];
__device__ int   g_cpi[NBH * 32 * SEQ];

// fast exp on the FMA pipe. |rel err| ~1e-7.
__device__ __forceinline__ float fexp(float x) {
    float y = x * 1.4426950408889634f;
    y = fminf(fmaxf(y, -126.0f), 126.0f);
    float t = y + 12582912.0f;
    int   e = __float_as_int(t) - 0x4B400000;
    float r = t - 12582912.0f;
    float f = y - r;
    float p = 1.535336188319500e-4f;
    p = fmaf(p, f, 1.339887440266574e-3f);
    p = fmaf(p, f, 9.618437357674640e-3f);
    p = fmaf(p, f, 5.550332471162809e-2f);
    p = fmaf(p, f, 2.402264791363012e-1f);
    p = fmaf(p, f, 6.931472028550421e-1f);
    p = fmaf(p, f, 1.0f);
    return p * __int_as_float((e + 127) << 23);
}

#define MMA_F16(d, a, b0, b1)                                               \
    asm volatile("mma.sync.aligned.m16n8k16.row.col.f32.f16.f16.f32 "        \
                 "{%0,%1,%2,%3}, {%4,%5,%6,%7}, {%8,%9}, {%0,%1,%2,%3};"     \
                 : "+f"((d)[0]), "+f"((d)[1]), "+f"((d)[2]), "+f"((d)[3])    \
                 : "r"((a)[0]), "r"((a)[1]), "r"((a)[2]), "r"((a)[3]),       \
                   "r"(b0), "r"(b1))

#define LDM4(r, addr)                                                        \
    asm volatile("ldmatrix.sync.aligned.m8n8.x4.shared.b16 {%0,%1,%2,%3}, [%4];" \
                 : "=r"((r)[0]), "=r"((r)[1]), "=r"((r)[2]), "=r"((r)[3])    \
                 : "r"(addr))

__device__ __forceinline__ uint32_t pack_h2(float a, float b) {
    __half2 t;
    t.x = __float2half_rn(a);
    t.y = __float2half_rn(b);
    return *(uint32_t*)&t;
}

#define FMA16(a, b, acc)                                                   \
    acc[0][0] = fmaf(a.x, b.x, acc[0][0]); acc[0][1] = fmaf(a.x, b.y, acc[0][1]); \
    acc[0][2] = fmaf(a.x, b.z, acc[0][2]); acc[0][3] = fmaf(a.x, b.w, acc[0][3]); \
    acc[1][0] = fmaf(a.y, b.x, acc[1][0]); acc[1][1] = fmaf(a.y, b.y, acc[1][1]); \
    acc[1][2] = fmaf(a.y, b.z, acc[1][2]); acc[1][3] = fmaf(a.y, b.w, acc[1][3]); \
    acc[2][0] = fmaf(a.z, b.x, acc[2][0]); acc[2][1] = fmaf(a.z, b.y, acc[2][1]); \
    acc[2][2] = fmaf(a.z, b.z, acc[2][2]); acc[2][3] = fmaf(a.z, b.w, acc[2][3]); \
    acc[3][0] = fmaf(a.w, b.x, acc[3][0]); acc[3][1] = fmaf(a.w, b.y, acc[3][1]); \
    acc[3][2] = fmaf(a.w, b.z, acc[3][2]); acc[3][3] = fmaf(a.w, b.w, acc[3][3]);

// ---------------- projection GEMM (FFMA) ---------------------------------
__global__ void proj_kernel(const float* __restrict__ A,
                            const float* __restrict__ W,
                            float* __restrict__ outPlain, int mode)
{
    __shared__ float As[16][68];
    __shared__ float Bs[16][68];
    const int tid = threadIdx.x;
    const int r0 = blockIdx.y << 6, c0 = blockIdx.x << 6;
    const int lr = tid >> 2;
    const int lc = (tid & 3) << 2;
    const float* Ap = A + (size_t)(r0 + lr) * CDIM + lc;
    const float* Wp = W + (size_t)(c0 + lr) * CDIM + lc;
    const int ty = tid >> 4, tx = tid & 15;
    float acc[4][4] = {};

    for (int k0 = 0; k0 < CDIM; k0 += 16) {
        float4 av = *(const float4*)(Ap + k0);
        float4 bv = *(const float4*)(Wp + k0);
        __syncthreads();
        As[lc + 0][lr] = av.x; As[lc + 1][lr] = av.y;
        As[lc + 2][lr] = av.z; As[lc + 3][lr] = av.w;
        Bs[lc + 0][lr] = bv.x; Bs[lc + 1][lr] = bv.y;
        Bs[lc + 2][lr] = bv.z; Bs[lc + 3][lr] = bv.w;
        __syncthreads();
#pragma unroll
        for (int k = 0; k < 16; k++) {
            float4 a = *(const float4*)&As[k][ty << 2];
            float4 b = *(const float4*)&Bs[k][tx << 2];
            FMA16(a, b, acc)
        }
    }

    if (mode == 2) {
#pragma unroll
        for (int i = 0; i < 4; i++) {
            int row = r0 + (ty << 2) + i;
            int b = row >> 11, n = row & 2047;
#pragma unroll
            for (int j = 0; j < 4; j++) {
                int col = c0 + (tx << 2) + j;
                int h = col >> 6, d = col & 63;
                g_Vt[(size_t)(((b << 3) + h) * HDIM + d) * SEQ + n] = acc[i][j];
            }
        }
    } else if (mode < 2) {
        float* OH = (mode == 0) ? g_Qh : g_Kh;
#pragma unroll
        for (int i = 0; i < 4; i++) {
            int row = r0 + (ty << 2) + i;
            int b = row >> 11, n = row & 2047;
#pragma unroll
            for (int j = 0; j < 4; j++) {
                int col = c0 + (tx << 2) + j;
                int h = col >> 6, d = col & 63;
                OH[(((b << 3) + h) * SEQ + n) * HDIM + d] = acc[i][j];
            }
        }
    } else {
#pragma unroll
        for (int i = 0; i < 4; i++) {
            int row = r0 + (ty << 2) + i;
            float4 o = make_float4(acc[i][0], acc[i][1], acc[i][2], acc[i][3]);
            *(float4*)&outPlain[(size_t)row * CDIM + c0 + (tx << 2)] = o;
        }
    }
}

// ---------------- fp32 -> fp16 split-2 planes ----------------------------
__global__ void cvt_split_kernel(const float* __restrict__ in,
                                 __half* __restrict__ out, int n)
{
    int i = blockIdx.x * blockDim.x + threadIdx.x;
    if (i >= n) return;
    float x = in[i];
    __half h = __float2half_rn(x);
    out[i] = h;
    out[n + i] = __float2half_rn(x - __half2float(h));
}

// ---- S = (Qh @ Kh^T)*SCALE via fp16 split-2 MMA + fused tile argmax -----
__global__ void __launch_bounds__(128) qk_mma_kernel()
{
    __shared__ __align__(16) unsigned char smraw[6 * PLANE * 2];  // 18432 B
    __half* sAB = (__half*)smraw;
    float* Ssm = (float*)smraw;                                   // 64x68 fp32 epilogue

    const int bh = blockIdx.z;
    const int r0 = blockIdx.y << 6, c0 = blockIdx.x << 6;
    const int tid = threadIdx.x, lane = tid & 31, w = tid >> 5;
    const int wm = (w & 1) << 5, wn = (w >> 1) << 5;

    const size_t qoff = (size_t)bh * SEQ * HDIM + (size_t)(r0 + (tid >> 1)) * HDIM + (tid & 1) * 8;
    const size_t koff = (size_t)bh * SEQ * HDIM + (size_t)(c0 + (tid >> 1)) * HDIM + (tid & 1) * 8;
    const __half* qp[2] = { g_Qh2 + qoff, g_Qh2 + (size_t)NQe + qoff };
    const __half* kp[2] = { g_Kh2 + koff, g_Kh2 + (size_t)NQe + koff };
    const int sts = (tid >> 1) * KP + (tid & 1) * 8;

    uint32_t sbase = (uint32_t)__cvta_generic_to_shared(sAB);
    const int lrow = (lane & 7) + ((lane >> 3) & 1) * 8;
    const int lk = (lane >> 4) * 8;
    uint32_t adA[2][2], adB[2][2];
#pragma unroll
    for (int p = 0; p < 2; p++)
#pragma unroll
        for (int t = 0; t < 2; t++) {
            adA[p][t] = sbase + 2 * (p * PLANE + (wm + 16 * t + lrow) * KP + lk);
            adB[p][t] = sbase + 2 * ((2 + p) * PLANE + (wn + 16 * t + lrow) * KP + lk);
        }

    float acc[2][4][4] = {};

#pragma unroll 1
    for (int ks = 0; ks < 4; ks++) {
        uint4 qv[2], kv[2];
#pragma unroll
        for (int p = 0; p < 2; p++) {
            qv[p] = *(const uint4*)(qp[p] + ks * 16);
            kv[p] = *(const uint4*)(kp[p] + ks * 16);
        }
        __syncthreads();
#pragma unroll
        for (int p = 0; p < 2; p++) {
            *(uint4*)&sAB[p * PLANE + sts] = qv[p];
            *(uint4*)&sAB[(2 + p) * PLANE + sts] = kv[p];
        }
        __syncthreads();

        uint32_t afr[2][2][4], bfr[2][2][4];
#pragma unroll
        for (int p = 0; p < 2; p++)
#pragma unroll
            for (int t = 0; t < 2; t++) { LDM4(afr[p][t], adA[p][t]); LDM4(bfr[p][t], adB[p][t]); }

        // split-2 combos: hh, hl, lh
        const int pa[3] = {0, 0, 1};
        const int pb[3] = {0, 1, 0};
#pragma unroll
        for (int c = 0; c < 3; c++)
#pragma unroll
            for (int mt = 0; mt < 2; mt++)
#pragma unroll
                for (int nt = 0; nt < 4; nt++) {
                    int n2 = nt >> 1, j = nt & 1;
                    MMA_F16(acc[mt][nt], afr[pa[c]][mt], bfr[pb[c]][n2][j], bfr[pb[c]][n2][j + 2]);
                }
    }

    __syncthreads();
#pragma unroll
    for (int mt = 0; mt < 2; mt++) {
        int row0 = wm + 16 * mt + (lane >> 2);
#pragma unroll
        for (int nt = 0; nt < 4; nt++) {
            int col = wn + 8 * nt + 2 * (lane & 3);
            *(float2*)&Ssm[row0 * 68 + col] =
                make_float2(acc[mt][nt][0] * QKSCALE, acc[mt][nt][1] * QKSCALE);
            *(float2*)&Ssm[(row0 + 8) * 68 + col] =
                make_float2(acc[mt][nt][2] * QKSCALE, acc[mt][nt][3] * QKSCALE);
        }
    }
    __syncthreads();

    float* Sp = g_S + (size_t)bh * SEQ * SEQ;
    {
        int row = tid >> 1, cb = (tid & 1) * 32;
#pragma unroll
        for (int i = 0; i < 8; i++)
            *(float4*)&Sp[(size_t)(r0 + row) * SEQ + c0 + cb + 4 * i] =
                *(const float4*)&Ssm[row * 68 + cb + 4 * i];
    }

    if (tid < 64) {
        float best = -3e38f; int bi = 0;
#pragma unroll
        for (int i = 0; i < 16; i++) {
            float4 v = *(const float4*)&Ssm[tid * 68 + 4 * i];
            if (v.x > best) { best = v.x; bi = 4 * i; }
            if (v.y > best) { best = v.y; bi = 4 * i + 1; }
            if (v.z > best) { best = v.z; bi = 4 * i + 2; }
            if (v.w > best) { best = v.w; bi = 4 * i + 3; }
        }
        size_t p = (size_t)((bh << 5) + blockIdx.x) * SEQ + r0 + tid;
        g_rpv[p] = best; g_rpi[p] = c0 + bi;
    } else {
        int c = tid - 64;
        float best = -3e38f; int bi = 0;
#pragma unroll 8
        for (int i = 0; i < 64; i++) {
            float v = Ssm[i * 68 + c];
            if (v > best) { best = v; bi = i; }
        }
        size_t p = (size_t)((bh << 5) + blockIdx.y) * SEQ + c0 + c;
        g_cpv[p] = best; g_cpi[p] = r0 + bi;
    }
}

// ---------------- reduce 32 partials -> q2k and k2q ----------------------
__global__ void argmax_reduce_kernel()
{
    int gid = blockIdx.x * blockDim.x + threadIdx.x;
    int which = gid >= NBH * SEQ;
    int i = gid & (NBH * SEQ - 1);
    int bh = i >> 11, n = i & 2047;
    const float* pv = which ? g_cpv : g_rpv;
    const int*   pi = which ? g_cpi : g_rpi;
    float v = -3e38f; int idx = 0;
#pragma unroll 8
    for (int t = 0; t < 32; t++) {
        size_t p = (size_t)((bh << 5) + t) * SEQ + n;
        float ov = pv[p];
        if (ov > v) { v = ov; idx = pi[p]; }
    }
    (which ? g_k2q : g_q2k)[i] = idx;
}

// ---------------- cycle consistency -> additive mask ---------------------
__global__ void asso_kernel(const int* __restrict__ smask,
                            const float* __restrict__ svalid)
{
    int i = blockIdx.x * blockDim.x + threadIdx.x;
    int bh = i >> 11, m = i & 2047;
    int b = bh >> 3;
    int kq = g_k2q[i];
    int remap = g_q2k[(bh << 11) + kq];
    float valid = (smask[(b << 11) + m] == smask[(b << 11) + remap])
                      ? svalid[(b << 11) + m] : 1.0f;
    g_madd[i] = valid * -10000.0f;
}

// ---- fused exp + online row-sum + P@V via fp16 split-2 mma.sync ---------
__global__ void __launch_bounds__(128) av_mma_kernel()
{
    __shared__ __align__(16) __half sAB[4 * PLANE];   // Ph,Pl,Vh,Vl
    __shared__ float sL[64];

    const int bh = blockIdx.y;
    const int n0 = blockIdx.x << 6;
    const int b = bh >> 3, h = bh & 7;
    const int tid = threadIdx.x, lane = tid & 31, w = tid >> 5;
    const int wm = (w & 1) << 5, wn = (w >> 1) << 5;

    const float* Sp = g_S + (size_t)bh * SEQ * SEQ + (size_t)(n0 + (tid >> 1)) * SEQ + (tid & 1) * 8;
    const float* mp = g_madd + bh * SEQ + (tid & 1) * 8;
    const size_t voff = (size_t)bh * HDIM * SEQ + (size_t)(tid >> 1) * SEQ + (tid & 1) * 8;
    const __half* vp[2] = { g_Vt2 + voff, g_Vt2 + (size_t)NQe + voff };
    const int sts = (tid >> 1) * KP + (tid & 1) * 8;

    uint32_t sbase = (uint32_t)__cvta_generic_to_shared(sAB);
    const int lrow = (lane & 7) + ((lane >> 3) & 1) * 8;
    const int lk = (lane >> 4) * 8;
    uint32_t adA[2][2], adB[2][2];
#pragma unroll
    for (int p = 0; p < 2; p++)
#pragma unroll
        for (int t = 0; t < 2; t++) {
            adA[p][t] = sbase + 2 * (p * PLANE + (wm + 16 * t + lrow) * KP + lk);
            adB[p][t] = sbase + 2 * ((2 + p) * PLANE + (wn + 16 * t + lrow) * KP + lk);
        }

    float acc[2][4][4] = {};
    float runL = 0.0f;

#pragma unroll 1
    for (int ks = 0; ks < 128; ks++) {
        float4 s0 = *(const float4*)(Sp + ks * 16);
        float4 s1 = *(const float4*)(Sp + ks * 16 + 4);
        float4 m0 = *(const float4*)(mp + ks * 16);
        float4 m1 = *(const float4*)(mp + ks * 16 + 4);
        uint4 v0 = *(const uint4*)(vp[0] + ks * 16);
        uint4 v1 = *(const uint4*)(vp[1] + ks * 16);

        float pv[8];
        pv[0] = fexp(s0.x + m0.x); pv[1] = fexp(s0.y + m0.y);
        pv[2] = fexp(s0.z + m0.z); pv[3] = fexp(s0.w + m0.w);
        pv[4] = fexp(s1.x + m1.x); pv[5] = fexp(s1.y + m1.y);
        pv[6] = fexp(s1.z + m1.z); pv[7] = fexp(s1.w + m1.w);
        runL += ((pv[0] + pv[1]) + (pv[2] + pv[3])) + ((pv[4] + pv[5]) + (pv[6] + pv[7]));

        uint4 ph, pl;
        float hs[8];
#pragma unroll
        for (int i = 0; i < 8; i++)
            hs[i] = __half2float(__float2half_rn(pv[i]));
        ph.x = pack_h2(pv[0], pv[1]); ph.y = pack_h2(pv[2], pv[3]);
        ph.z = pack_h2(pv[4], pv[5]); ph.w = pack_h2(pv[6], pv[7]);
        pl.x = pack_h2(pv[0] - hs[0], pv[1] - hs[1]);
        pl.y = pack_h2(pv[2] - hs[2], pv[3] - hs[3]);
        pl.z = pack_h2(pv[4] - hs[4], pv[5] - hs[5]);
        pl.w = pack_h2(pv[6] - hs[6], pv[7] - hs[7]);

        __syncthreads();
        *(uint4*)&sAB[0 * PLANE + sts] = ph;
        *(uint4*)&sAB[1 * PLANE + sts] = pl;
        *(uint4*)&sAB[2 * PLANE + sts] = v0;
        *(uint4*)&sAB[3 * PLANE + sts] = v1;
        __syncthreads();

        uint32_t afr[2][2][4], bfr[2][2][4];
#pragma unroll
        for (int p = 0; p < 2; p++)
#pragma unroll
            for (int t = 0; t < 2; t++) { LDM4(afr[p][t], adA[p][t]); LDM4(bfr[p][t], adB[p][t]); }

        const int pa[3] = {0, 0, 1};
        const int pb[3] = {0, 1, 0};
#pragma unroll
        for (int c = 0; c < 3; c++)
#pragma unroll
            for (int mt = 0; mt < 2; mt++)
#pragma unroll
                for (int nt = 0; nt < 4; nt++) {
                    int n2 = nt >> 1, j = nt & 1;
                    MMA_F16(acc[mt][nt], afr[pa[c]][mt], bfr[pb[c]][n2][j], bfr[pb[c]][n2][j + 2]);
                }
    }

    runL += __shfl_xor_sync(0xffffffffu, runL, 1);
    if (!(tid & 1)) sL[tid >> 1] = runL;
    __syncthreads();

#pragma unroll
    for (int mt = 0; mt < 2; mt++) {
        int row0 = wm + 16 * mt + (lane >> 2);
        float inv0 = 1.0f / sL[row0];
        float inv1 = 1.0f / sL[row0 + 8];
#pragma unroll
        for (int nt = 0; nt < 4; nt++) {
            int col = wn + 8 * nt + 2 * (lane & 3);
            int n = n0 + row0;
            *(float2*)&g_X[(size_t)(b * SEQ + n) * CDIM + h * HDIM + col] =
                make_float2(acc[mt][nt][0] * inv0, acc[mt][nt][1] * inv0);
            *(float2*)&g_X[(size_t)(b * SEQ + n + 8) * CDIM + h * HDIM + col] =
                make_float2(acc[mt][nt][2] * inv1, acc[mt][nt][3] * inv1);
        }
    }
}

// ---------------- launcher ------------------------------------------------
extern "C" void kernel_launch(void* const* d_in, const int* in_sizes, int n_in,
                              void* d_out, int out_size)
{
    const float* q   = (const float*)d_in[0];
    const float* k   = (const float*)d_in[1];
    const float* v   = (const float*)d_in[2];
    const float* svm = (const float*)d_in[3];
    const int*   sm  = (const int*)d_in[4];
    const float* Wq  = (const float*)d_in[5];
    const float* Wk  = (const float*)d_in[6];
    const float* Wv  = (const float*)d_in[7];
    const float* Wp  = (const float*)d_in[8];
    float* out = (float*)d_out;

    float *X, *QhF, *KhF, *VtF;
    __half *Q2, *K2, *V2;
    cudaGetSymbolAddress((void**)&X, g_X);
    cudaGetSymbolAddress((void**)&QhF, g_Qh);
    cudaGetSymbolAddress((void**)&KhF, g_Kh);
    cudaGetSymbolAddress((void**)&VtF, g_Vt);
    cudaGetSymbolAddress((void**)&Q2, g_Qh2);
    cudaGetSymbolAddress((void**)&K2, g_Kh2);
    cudaGetSymbolAddress((void**)&V2, g_Vt2);

    dim3 gp(CDIM / 64, (2 * SEQ) / 64);      // (8, 64)
    proj_kernel<<<gp, 256>>>(q, Wq, nullptr, 0);
    proj_kernel<<<gp, 256>>>(k, Wk, nullptr, 1);
    proj_kernel<<<gp, 256>>>(v, Wv, nullptr, 2);

    int cvtb = NQe / 256;
    cvt_split_kernel<<<cvtb, 256>>>(QhF, Q2, NQe);
    cvt_split_kernel<<<cvtb, 256>>>(KhF, K2, NQe);
    cvt_split_kernel<<<cvtb, 256>>>(VtF, V2, NQe);

    qk_mma_kernel<<<dim3(SEQ / 64, SEQ / 64, NBH), 128>>>();

    argmax_reduce_kernel<<<(2 * NBH * SEQ) / 256, 256>>>();
    asso_kernel<<<(NBH * SEQ) / 256, 256>>>(sm, svm);

    av_mma_kernel<<<dim3(SEQ / 64, NBH), 128>>>();

    proj_kernel<<<gp, 256>>>(X, Wp, out, 3);
}